// round 1
// baseline (speedup 1.0000x reference)
#include <cuda_runtime.h>

#define BSZv   16
#define DIMv   128
#define KP1v   65537
#define NDATAv 1000000

// Flag: 1 if y/idx are stored as int64, 0 if int32 (JAX x64-disabled case).
static __device__ int g_is64;

__global__ void detect_kernel(const void* __restrict__ idx) {
    const long long* p = (const long long*)idx;
    bool is64 = true;
    #pragma unroll
    for (int i = 0; i < 4; i++) {
        long long v = p[i];
        if (v < 0 || v >= (long long)NDATAv) is64 = false;
    }
    g_is64 = is64 ? 1 : 0;
}

__device__ __forceinline__ long long load_index(const void* __restrict__ p,
                                                long long i, int is64) {
    if (is64) return ((const long long*)p)[i];
    return (long long)((const int*)p)[i];
}

// One warp processes 8 (b,k) pairs: 8 independent coalesced 512B row gathers
// (lane -> float4), then 8 interleaved butterfly reductions.
__global__ void __launch_bounds__(256) logits_kernel(
    const float* __restrict__ x, const void* __restrict__ y,
    const void* __restrict__ idx, const float* __restrict__ memory,
    float* __restrict__ logits)
{
    const int is64 = g_is64;
    const int b    = blockIdx.y;
    const int lane = threadIdx.x & 31;
    const int warp = threadIdx.x >> 5;

    // x[b] row held in registers: lane owns float4
    const float4 xv = reinterpret_cast<const float4*>(x)[b * 32 + lane];

    const int k0 = (blockIdx.x * 8 + warp) * 8;   // first of 8 pairs

    // lanes 0..7 fetch the 8 indices (contiguous), broadcast via shfl
    long long r = 0;
    {
        int kk = k0 + lane;
        if (lane < 8 && kk < KP1v) {
            r = (kk == 0) ? load_index(y, b, is64)
                          : load_index(idx, (long long)b * KP1v + kk, is64);
        }
    }
    long long rows[8];
    #pragma unroll
    for (int p = 0; p < 8; p++) rows[p] = __shfl_sync(0xffffffffu, r, p);

    // 8 independent gathers -> 8 partial dots
    float acc[8];
    #pragma unroll
    for (int p = 0; p < 8; p++) {
        float4 wv = make_float4(0.f, 0.f, 0.f, 0.f);
        if (k0 + p < KP1v)
            wv = reinterpret_cast<const float4*>(memory)[rows[p] * 32 + lane];
        acc[p] = wv.x * xv.x + wv.y * xv.y + wv.z * xv.z + wv.w * xv.w;
    }

    // interleaved butterfly reductions (keeps 8 shuffles in flight per step)
    #pragma unroll
    for (int off = 16; off >= 1; off >>= 1) {
        #pragma unroll
        for (int p = 0; p < 8; p++)
            acc[p] += __shfl_down_sync(0xffffffffu, acc[p], off);
    }

    if (lane == 0) {
        const float t_inv = 1.0f / 0.07f;
        #pragma unroll
        for (int p = 0; p < 8; p++)
            if (k0 + p < KP1v)
                logits[(long long)b * KP1v + k0 + p] = acc[p] * t_inv;
    }
}

// 16 warps: warp b computes the EMA-renormalized row for y[b] and scatters it
// into the already-copied output bank. Also zeroes the 16 labels.
__global__ void __launch_bounds__(512) update_kernel(
    const float* __restrict__ x, const void* __restrict__ y,
    const float* __restrict__ memory, float* __restrict__ out)
{
    const int is64 = g_is64;
    float* labels  = out + (long long)BSZv * KP1v;
    float* out_mem = labels + BSZv;

    if (threadIdx.x < BSZv) labels[threadIdx.x] = 0.0f;  // int32 0 == f32 0.0 bits

    const int warp = threadIdx.x >> 5;   // = b, 0..15
    const int lane = threadIdx.x & 31;

    const long long row = load_index(y, warp, is64);
    const float4 mv = reinterpret_cast<const float4*>(memory)[row * 32 + lane];
    const float4 xv = reinterpret_cast<const float4*>(x)[warp * 32 + lane];

    float4 w = make_float4(0.5f * (mv.x + xv.x), 0.5f * (mv.y + xv.y),
                           0.5f * (mv.z + xv.z), 0.5f * (mv.w + xv.w));
    float ss = w.x * w.x + w.y * w.y + w.z * w.z + w.w * w.w;
    #pragma unroll
    for (int off = 16; off >= 1; off >>= 1)
        ss += __shfl_xor_sync(0xffffffffu, ss, off);

    const float inv = 1.0f / fmaxf(sqrtf(ss), 1e-12f);
    w.x *= inv; w.y *= inv; w.z *= inv; w.w *= inv;
    reinterpret_cast<float4*>(out_mem)[row * 32 + lane] = w;
}

extern "C" void kernel_launch(void* const* d_in, const int* in_sizes, int n_in,
                              void* d_out, int out_size)
{
    const float* x      = (const float*)d_in[0];
    const void*  y      = d_in[1];
    const void*  idx    = d_in[2];
    const float* memory = (const float*)d_in[3];
    float*       out    = (float*)d_out;

    (void)in_sizes; (void)n_in; (void)out_size;

    detect_kernel<<<1, 1>>>(idx);

    dim3 grid((KP1v + 63) / 64, BSZv);       // 1025 x 16 blocks, 64 pairs/block
    logits_kernel<<<grid, 256>>>(x, y, idx, memory, out);

    // bulk copy of the bank into the output, then overwrite the 16 rows
    float* out_mem = out + (long long)BSZv * KP1v + BSZv;
    cudaMemcpyAsync(out_mem, memory, (size_t)NDATAv * DIMv * sizeof(float),
                    cudaMemcpyDeviceToDevice, 0);

    update_kernel<<<1, 512>>>(x, y, memory, out);
}

// round 2
// speedup vs baseline: 1.0026x; 1.0026x over previous
#include <cuda_runtime.h>

#define BSZv   16
#define DIMv   128
#define K1v    65537
#define NDATAv 1000000
#define CAPv   12
#define NOVFv  65536
#define NENTv  (BSZv * K1v)          // 1,048,592

// Scratch (static __device__ arrays: the sanctioned no-alloc workaround)
static __device__ unsigned int g_counts[NDATAv + 1];   // [+1] = overflow counter
static __device__ unsigned int g_entries[NDATAv * CAPv];
static __device__ unsigned int g_ovf[NOVFv];

__device__ __forceinline__ int detect_is64(const void* __restrict__ idx) {
    const long long* p = (const long long*)idx;
    #pragma unroll
    for (int i = 0; i < 4; i++) {
        long long v = p[i];
        if (v < 0 || v >= (long long)NDATAv) return 0;
    }
    return 1;
}

__device__ __forceinline__ long long load_index(const void* __restrict__ p,
                                                long long i, int is64) {
    return is64 ? ((const long long*)p)[i] : (long long)((const int*)p)[i];
}

// Shared dot helper so main & overflow paths produce bit-identical logits.
__device__ __forceinline__ float warp_dot(float4 rv, float4 xv) {
    float a = rv.x * xv.x + rv.y * xv.y + rv.z * xv.z + rv.w * xv.w;
    #pragma unroll
    for (int off = 16; off >= 1; off >>= 1)
        a += __shfl_down_sync(0xffffffffu, a, off);
    return a;
}

__global__ void zero_kernel() {
    long long i = (long long)blockIdx.x * blockDim.x + threadIdx.x;
    long long n = NDATAv + 1;
    for (; i < n; i += (long long)gridDim.x * blockDim.x) g_counts[i] = 0u;
}

// One thread per (b,k) entry: scatter into per-row bucket lists.
__global__ void __launch_bounds__(256) build_kernel(const void* __restrict__ y,
                                                    const void* __restrict__ idx) {
    __shared__ int s_is64;
    if (threadIdx.x == 0) s_is64 = detect_is64(idx);
    __syncthreads();
    const int is64 = s_is64;

    long long e = (long long)blockIdx.x * blockDim.x + threadIdx.x;
    if (e >= NENTv) return;
    int b = (int)(e / K1v);
    int k = (int)(e - (long long)b * K1v);
    long long row = (k == 0) ? load_index(y, b, is64) : load_index(idx, e, is64);

    unsigned enc = ((unsigned)b << 17) | (unsigned)k;
    unsigned slot = atomicAdd(&g_counts[row], 1u);
    if (slot < CAPv) {
        g_entries[row * CAPv + slot] = enc;
    } else {
        unsigned o = atomicAdd(&g_counts[NDATAv], 1u);
        if (o < NOVFv) g_ovf[o] = enc;
    }
}

// Fused streaming pass: copy bank -> out (with EMA patch on the 16 y rows),
// compute all bucketed logits while each row sits in registers, write labels.
__global__ void __launch_bounds__(256) main_kernel(
    const float* __restrict__ x, const void* __restrict__ y,
    const void* __restrict__ idx, const float* __restrict__ memory,
    float* __restrict__ out)
{
    __shared__ float s_x[BSZv * DIMv];
    __shared__ long long s_y[BSZv];
    __shared__ int s_is64;

    if (threadIdx.x == 0) s_is64 = detect_is64(idx);
    __syncthreads();
    const int is64 = s_is64;
    for (int i = threadIdx.x; i < BSZv * DIMv; i += blockDim.x) s_x[i] = x[i];
    if (threadIdx.x < BSZv) s_y[threadIdx.x] = load_index(y, threadIdx.x, is64);
    __syncthreads();

    float* logits  = out;
    float* labels  = out + (long long)BSZv * K1v;
    float* out_mem = labels + BSZv;
    if (blockIdx.x == 0 && threadIdx.x < BSZv) labels[threadIdx.x] = 0.0f;

    const int lane = threadIdx.x & 31;
    const int warp = threadIdx.x >> 5;
    const float4* mem4 = (const float4*)memory;
    float4*       out4 = (float4*)out_mem;
    const float4* sx4  = (const float4*)s_x;
    const float t_inv  = 1.0f / 0.07f;

    const long long wstride = (long long)gridDim.x * 8;
    for (long long r = (long long)blockIdx.x * 8 + warp; r < NDATAv; r += wstride) {
        const float4 rv = __ldcs(&mem4[r * 32 + lane]);   // streaming: keep L2 for buckets

        // EMA patch if r is one of the 16 positives (last b wins, like .at[].set)
        int bmatch = -1;
        #pragma unroll
        for (int b = 0; b < BSZv; b++)
            if (s_y[b] == r) bmatch = b;

        float4 wv = rv;
        if (bmatch >= 0) {
            const float4 xv = sx4[bmatch * 32 + lane];
            wv = make_float4(0.5f * (rv.x + xv.x), 0.5f * (rv.y + xv.y),
                             0.5f * (rv.z + xv.z), 0.5f * (rv.w + xv.w));
            float ss = wv.x * wv.x + wv.y * wv.y + wv.z * wv.z + wv.w * wv.w;
            #pragma unroll
            for (int off = 16; off >= 1; off >>= 1)
                ss += __shfl_xor_sync(0xffffffffu, ss, off);
            const float inv = 1.0f / fmaxf(sqrtf(ss), 1e-12f);
            wv.x *= inv; wv.y *= inv; wv.z *= inv; wv.w *= inv;
        }
        __stcs(&out4[r * 32 + lane], wv);

        // logits for every (b,k) that referenced this row (old row value rv)
        unsigned cnt = g_counts[r];
        cnt = cnt > CAPv ? CAPv : cnt;
        for (unsigned j = 0; j < cnt; j++) {
            const unsigned enc = g_entries[r * CAPv + j];
            const int b = enc >> 17;
            const int k = enc & 0x1FFFF;
            const float a = warp_dot(rv, sx4[b * 32 + lane]);
            if (lane == 0) logits[(long long)b * K1v + k] = a * t_inv;
        }
    }
}

// Safety net: entries that overflowed the per-row buckets (expected: none).
__global__ void __launch_bounds__(256) ovf_kernel(
    const float* __restrict__ x, const float* __restrict__ memory,
    float* __restrict__ logits)
{
    const unsigned n = min(g_counts[NDATAv], (unsigned)NOVFv);
    if (n == 0) return;
    const int lane = threadIdx.x & 31;
    const int warp = threadIdx.x >> 5;
    const float4* mem4 = (const float4*)memory;
    const float4* x4   = (const float4*)x;
    const float t_inv  = 1.0f / 0.07f;

    for (unsigned i = warp; i < n; i += blockDim.x / 32) {
        const unsigned enc = g_ovf[i];
        const int b = enc >> 17;
        const int k = enc & 0x1FFFF;
        // row must be re-derived: encoded entries don't store it; recover via
        // logits slot -> we stored only (b,k), so re-read the index arrays is
        // needed. Instead: recompute row from logits position is impossible,
        // so we re-gather via the entry's own source below.
        // NOTE: row recovery handled by storing row in upper bits is not
        // possible (21+20 bits > 32). We instead re-read idx/y lazily here.
        // (n is ~always 0; correctness path only.)
        // row passed via g_ovf second half: see build — not needed since we
        // re-derive from idx in kernel_launch-provided pointers.
        (void)b; (void)k; (void)mem4; (void)x4; (void)t_inv; (void)logits;
    }
}

// Overflow with index re-read (real implementation).
__global__ void __launch_bounds__(256) ovf_kernel2(
    const float* __restrict__ x, const void* __restrict__ y,
    const void* __restrict__ idx, const float* __restrict__ memory,
    float* __restrict__ logits)
{
    __shared__ int s_is64;
    if (threadIdx.x == 0) s_is64 = detect_is64(idx);
    __syncthreads();
    const int is64 = s_is64;

    const unsigned n = min(g_counts[NDATAv], (unsigned)NOVFv);
    if (n == 0) return;
    const int lane = threadIdx.x & 31;
    const int warp = threadIdx.x >> 5;
    const float4* mem4 = (const float4*)memory;
    const float4* x4   = (const float4*)x;
    const float t_inv  = 1.0f / 0.07f;

    for (unsigned i = warp; i < n; i += blockDim.x / 32) {
        const unsigned enc = g_ovf[i];
        const int b = enc >> 17;
        const int k = enc & 0x1FFFF;
        const long long e = (long long)b * K1v + k;
        const long long row = (k == 0) ? load_index(y, b, is64)
                                       : load_index(idx, e, is64);
        const float4 rv = mem4[row * 32 + lane];
        const float a = warp_dot(rv, x4[b * 32 + lane]);
        if (lane == 0) logits[e] = a * t_inv;
    }
}

extern "C" void kernel_launch(void* const* d_in, const int* in_sizes, int n_in,
                              void* d_out, int out_size)
{
    const float* x      = (const float*)d_in[0];
    const void*  y      = d_in[1];
    const void*  idx    = d_in[2];
    const float* memory = (const float*)d_in[3];
    float*       out    = (float*)d_out;
    (void)in_sizes; (void)n_in; (void)out_size;

    zero_kernel<<<2048, 512>>>();
    build_kernel<<<(NENTv + 255) / 256, 256>>>(y, idx);
    main_kernel<<<16384, 256>>>(x, y, idx, memory, out);
    ovf_kernel2<<<1, 256>>>(x, y, idx, memory, out);
}

// round 4
// speedup vs baseline: 1.2151x; 1.2119x over previous
#include <cuda_runtime.h>

#define BSZv   16
#define DIMv   128
#define K1v    65537
#define NDATAv 1000000
#define CAPv   8
#define NOVFv  65536
#define NENTv  (BSZv * K1v)          // 1,048,592

static __device__ unsigned int g_counts[NDATAv + 4];   // [NDATAv] = overflow ctr
static __device__ unsigned int g_entries[(size_t)NDATAv * CAPv];
static __device__ unsigned int g_ovf[NOVFv];

__device__ __forceinline__ int detect_is64(const void* __restrict__ idx) {
    const long long* p = (const long long*)idx;
    #pragma unroll
    for (int i = 0; i < 4; i++) {
        long long v = p[i];
        if (v < 0 || v >= (long long)NDATAv) return 0;
    }
    return 1;
}

__device__ __forceinline__ long long load_index(const void* __restrict__ p,
                                                long long i, int is64) {
    return is64 ? ((const long long*)p)[i] : (long long)((const int*)p)[i];
}

__device__ __forceinline__ float warp_dot(float4 rv, float4 xv) {
    float a = rv.x * xv.x + rv.y * xv.y + rv.z * xv.z + rv.w * xv.w;
    #pragma unroll
    for (int off = 16; off >= 1; off >>= 1)
        a += __shfl_down_sync(0xffffffffu, a, off);
    return a;
}

__global__ void zero_kernel() {
    unsigned i = blockIdx.x * blockDim.x + threadIdx.x;
    if (i < NDATAv + 4) g_counts[i] = 0u;
}

__global__ void __launch_bounds__(256) build_kernel(const void* __restrict__ y,
                                                    const void* __restrict__ idx) {
    __shared__ int s_is64;
    if (threadIdx.x == 0) s_is64 = detect_is64(idx);
    __syncthreads();
    const int is64 = s_is64;

    long long e = (long long)blockIdx.x * blockDim.x + threadIdx.x;
    if (e >= NENTv) return;
    int b = (int)(e / K1v);
    int k = (int)(e - (long long)b * K1v);
    long long row = (k == 0) ? load_index(y, b, is64) : load_index(idx, e, is64);

    unsigned enc  = ((unsigned)b << 17) | (unsigned)k;
    unsigned slot = atomicAdd(&g_counts[row], 1u);
    if (slot < CAPv) {
        g_entries[(size_t)row * CAPv + slot] = enc;
    } else {
        unsigned o = atomicAdd(&g_counts[NDATAv], 1u);
        if (o < NOVFv) g_ovf[o] = enc;
    }
}

// Streaming pass: copy bank -> out while computing every bucketed logit with
// the row already in registers. 4 rows/warp/iter, all loads front-batched.
__global__ void __launch_bounds__(256) main_kernel(
    const float* __restrict__ x, const float* __restrict__ memory,
    float* __restrict__ out)
{
    __shared__ float s_x[BSZv * DIMv];
    for (int i = threadIdx.x; i < BSZv * DIMv; i += blockDim.x) s_x[i] = x[i];
    __syncthreads();

    float* logits  = out;
    float* labels  = out + (long long)BSZv * K1v;
    float* out_mem = labels + BSZv;
    if (blockIdx.x == 0 && threadIdx.x < BSZv) labels[threadIdx.x] = 0.0f;

    const int lane = threadIdx.x & 31;
    const int warp = threadIdx.x >> 5;
    const float4* mem4 = (const float4*)memory;
    float4*       out4 = (float4*)out_mem;
    const float4* sx4  = (const float4*)s_x;
    const float t_inv  = 1.0f / 0.07f;

    const long long base0  = ((long long)blockIdx.x * 8 + warp) * 4;
    const long long stride = (long long)gridDim.x * 32;

    for (long long r0 = base0; r0 < NDATAv; r0 += stride) {
        // ---- front-batched loads: 4 rows + counts + entry slots (MLP ~9) ----
        const uint4 cnt4 = *(const uint4*)(g_counts + r0);
        uint4 ent[4];
        #pragma unroll
        for (int i = 0; i < 4; i++)
            ent[i] = *(const uint4*)(g_entries + (size_t)(r0 + i) * CAPv);
        float4 rv[4];
        #pragma unroll
        for (int i = 0; i < 4; i++)
            rv[i] = __ldcs(&mem4[(r0 + i) * 32 + lane]);

        // ---- stream out (EMA rows patched later by update_kernel) ----
        #pragma unroll
        for (int i = 0; i < 4; i++)
            __stcs(&out4[(r0 + i) * 32 + lane], rv[i]);

        const unsigned cnts[4] = {cnt4.x, cnt4.y, cnt4.z, cnt4.w};
        #pragma unroll
        for (int i = 0; i < 4; i++) {
            const unsigned c = cnts[i] > CAPv ? CAPv : cnts[i];
            if (c == 0) continue;
            const unsigned s0 = ent[i].x, s1 = ent[i].y, s2 = ent[i].z, s3 = ent[i].w;
            #pragma unroll
            for (int j = 0; j < 4; j++) {
                if (j < (int)c) {
                    const unsigned enc = (j == 0) ? s0 : (j == 1) ? s1
                                       : (j == 2) ? s2 : s3;
                    const int b = enc >> 17;
                    const int k = enc & 0x1FFFF;
                    const float a = warp_dot(rv[i], sx4[b * 32 + lane]);
                    if (lane == 0) logits[(long long)b * K1v + k] = a * t_inv;
                }
            }
            for (unsigned j = 4; j < c; j++) {          // rare (P ~ 2e-3/row)
                const unsigned enc = g_entries[(size_t)(r0 + i) * CAPv + j];
                const int b = enc >> 17;
                const int k = enc & 0x1FFFF;
                const float a = warp_dot(rv[i], sx4[b * 32 + lane]);
                if (lane == 0) logits[(long long)b * K1v + k] = a * t_inv;
            }
        }
    }
}

// Patch the 16 EMA rows in the output bank (runs after main, stream-ordered).
__global__ void __launch_bounds__(512) update_kernel(
    const float* __restrict__ x, const void* __restrict__ y,
    const void* __restrict__ idx, const float* __restrict__ memory,
    float* __restrict__ out)
{
    __shared__ int s_is64;
    if (threadIdx.x == 0) s_is64 = detect_is64(idx);
    __syncthreads();
    const int is64 = s_is64;

    float* out_mem = out + (long long)BSZv * K1v + BSZv;
    const int warp = threadIdx.x >> 5;   // = b
    const int lane = threadIdx.x & 31;

    const long long row = load_index(y, warp, is64);
    const float4 mv = ((const float4*)memory)[row * 32 + lane];
    const float4 xv = ((const float4*)x)[warp * 32 + lane];

    float4 w = make_float4(0.5f * (mv.x + xv.x), 0.5f * (mv.y + xv.y),
                           0.5f * (mv.z + xv.z), 0.5f * (mv.w + xv.w));
    float ss = w.x * w.x + w.y * w.y + w.z * w.z + w.w * w.w;
    #pragma unroll
    for (int off = 16; off >= 1; off >>= 1)
        ss += __shfl_xor_sync(0xffffffffu, ss, off);
    const float inv = 1.0f / fmaxf(sqrtf(ss), 1e-12f);
    w.x *= inv; w.y *= inv; w.z *= inv; w.w *= inv;
    ((float4*)out_mem)[row * 32 + lane] = w;
}

// Overflow safety net (expected n == 0 with CAP=8); launched wide regardless.
__global__ void __launch_bounds__(256) ovf_kernel(
    const float* __restrict__ x, const void* __restrict__ y,
    const void* __restrict__ idx, const float* __restrict__ memory,
    float* __restrict__ logits)
{
    const unsigned n = min(g_counts[NDATAv], (unsigned)NOVFv);
    if (n == 0) return;
    __shared__ int s_is64;
    if (threadIdx.x == 0) s_is64 = detect_is64(idx);
    __syncthreads();
    const int is64 = s_is64;

    const int lane = threadIdx.x & 31;
    const unsigned gw = (blockIdx.x * blockDim.x + threadIdx.x) >> 5;
    const unsigned nw = (gridDim.x * blockDim.x) >> 5;
    const float4* mem4 = (const float4*)memory;
    const float4* x4   = (const float4*)x;
    const float t_inv  = 1.0f / 0.07f;

    for (unsigned i = gw; i < n; i += nw) {
        const unsigned enc = g_ovf[i];
        const int b = enc >> 17;
        const int k = enc & 0x1FFFF;
        const long long e = (long long)b * K1v + k;
        const long long row = (k == 0) ? load_index(y, b, is64)
                                       : load_index(idx, e, is64);
        const float a = warp_dot(mem4[row * 32 + lane], x4[b * 32 + lane]);
        if (lane == 0) logits[e] = a * t_inv;
    }
}

extern "C" void kernel_launch(void* const* d_in, const int* in_sizes, int n_in,
                              void* d_out, int out_size)
{
    const float* x      = (const float*)d_in[0];
    const void*  y      = d_in[1];
    const void*  idx    = d_in[2];
    const float* memory = (const float*)d_in[3];
    float*       out    = (float*)d_out;
    (void)in_sizes; (void)n_in; (void)out_size;

    zero_kernel<<<(NDATAv + 4 + 255) / 256, 256>>>();
    build_kernel<<<(NENTv + 255) / 256, 256>>>(y, idx);
    main_kernel<<<4096, 256>>>(x, memory, out);
    update_kernel<<<1, 512>>>(x, y, idx, memory, out);
    ovf_kernel<<<128, 256>>>(x, y, idx, memory, out);
}